// round 1
// baseline (speedup 1.0000x reference)
#include <cuda_runtime.h>
#include <math.h>

#define BB 32
#define NN 1024
#define KNN 20
#define RTOT (BB*NN)          // 32768 rows
#define NEG_SLOPE 0.2f
#define EPS 1e-5f

// ---------------- static scratch (allocation-free rule) ----------------
__device__ float g_pd[(size_t)BB*NN*NN];     // 128 MB: pairwise dists / layer-5 h
__device__ int   g_idx[(size_t)RTOT*KNN];
__device__ float g_p[(size_t)RTOT*256];
__device__ float g_q[(size_t)RTOT*256];
__device__ float g_hmax[(size_t)RTOT*256];
__device__ float g_cat[(size_t)RTOT*512];    // [x1|x2|x3|x4] per row
__device__ float g_wq[1024*512];
__device__ float g_xx[RTOT];
__device__ float g_sum[1024];
__device__ float g_sumsq[1024];
__device__ float g_bmax[RTOT];

// ---------------- kernels ----------------

__global__ void k_xx(const float* __restrict__ F, int fs, int C, float* __restrict__ xx) {
    int r = blockIdx.x*blockDim.x + threadIdx.x;
    if (r >= RTOT) return;
    const float* f = F + (size_t)r*fs;
    float s = 0.f;
    for (int c = 0; c < C; c++) { float v = f[c]; s += v*v; }
    xx[r] = s;
}

// pd[b,n,m] = 2*<x_n,x_m> - ||x_n||^2 - ||x_m||^2   (32x32 tiles)
__global__ void k_pair(const float* __restrict__ F, int fs, int C,
                       const float* __restrict__ xx, float* __restrict__ pd) {
    int b = blockIdx.z;
    int tx = threadIdx.x, ty = threadIdx.y;
    int n = blockIdx.y*32 + ty;
    int m = blockIdx.x*32 + tx;
    __shared__ float As[32][33], Bs[32][33];
    const float* Fb = F + (size_t)b*NN*fs;
    float acc = 0.f;
    for (int c0 = 0; c0 < C; c0 += 32) {
        int c = c0 + tx;
        As[ty][tx] = (c < C) ? Fb[(size_t)(blockIdx.y*32+ty)*fs + c] : 0.f;
        Bs[ty][tx] = (c < C) ? Fb[(size_t)(blockIdx.x*32+ty)*fs + c] : 0.f;
        __syncthreads();
        #pragma unroll
        for (int cc = 0; cc < 32; cc++) acc += As[ty][cc]*Bs[tx][cc];
        __syncthreads();
    }
    pd[(size_t)b*NN*NN + (size_t)n*NN + m] = 2.f*acc - xx[b*NN + n] - xx[b*NN + m];
}

// top-20 (largest value, tie -> lower index, matching jax.lax.top_k)
__global__ void k_topk(const float* __restrict__ pd, int* __restrict__ idx) {
    int row = blockIdx.x;
    int tid = threadIdx.x;
    __shared__ float sd[NN];
    __shared__ float rv[256];
    __shared__ int   ri[256];
    const float* prow = pd + (size_t)row*NN;
    for (int i = tid; i < NN; i += 256) sd[i] = prow[i];
    __syncthreads();
    for (int it = 0; it < KNN; it++) {
        float bv = -INFINITY; int bi = 0x7fffffff;
        for (int i = tid; i < NN; i += 256) {
            float v = sd[i];
            if (v > bv || (v == bv && i < bi)) { bv = v; bi = i; }
        }
        rv[tid] = bv; ri[tid] = bi;
        __syncthreads();
        for (int s = 128; s > 0; s >>= 1) {
            if (tid < s) {
                float v2 = rv[tid+s]; int i2 = ri[tid+s];
                if (v2 > rv[tid] || (v2 == rv[tid] && i2 < ri[tid])) { rv[tid] = v2; ri[tid] = i2; }
            }
            __syncthreads();
        }
        if (tid == 0) { idx[(size_t)row*KNN + it] = ri[0]; sd[ri[0]] = -INFINITY; }
        __syncthreads();
    }
}

__global__ void k_wq(const float* __restrict__ W, int C, int O, float* __restrict__ wq) {
    int i = blockIdx.x*blockDim.x + threadIdx.x;
    if (i >= O*C) return;
    int o = i / C, c = i - o*C;
    wq[i] = W[(size_t)o*2*C + C + c] - W[(size_t)o*2*C + c];
}

// out[m,o] = sum_k A[m,k]*Bw[o,k]; BM=BO=64, BK=16, 4x4 per thread
__global__ void k_sgemm(const float* __restrict__ A, int lda,
                        const float* __restrict__ Bw, int ldb,
                        float* __restrict__ Cout, int Kdim, int O) {
    __shared__ float As[16][65], Ws[16][65];
    int tx = threadIdx.x, ty = threadIdx.y;
    int tid = ty*16 + tx;
    int m0 = blockIdx.x*64, o0 = blockIdx.y*64;
    float acc[4][4];
    #pragma unroll
    for (int i = 0; i < 4; i++)
        #pragma unroll
        for (int j = 0; j < 4; j++) acc[i][j] = 0.f;

    for (int k0 = 0; k0 < Kdim; k0 += 16) {
        #pragma unroll
        for (int r = 0; r < 4; r++) {
            int i  = tid + r*256;
            int kk = i & 15, mm = i >> 4;
            As[kk][mm] = (k0+kk < Kdim) ? A[(size_t)(m0+mm)*lda + k0+kk] : 0.f;
            Ws[kk][mm] = (k0+kk < Kdim) ? Bw[(size_t)(o0+mm)*ldb + k0+kk] : 0.f;
        }
        __syncthreads();
        #pragma unroll
        for (int kk = 0; kk < 16; kk++) {
            float a[4], bfr[4];
            #pragma unroll
            for (int i = 0; i < 4; i++) a[i] = As[kk][ty*4 + i];
            #pragma unroll
            for (int j = 0; j < 4; j++) bfr[j] = Ws[kk][tx*4 + j];
            #pragma unroll
            for (int i = 0; i < 4; i++)
                #pragma unroll
                for (int j = 0; j < 4; j++) acc[i][j] += a[i]*bfr[j];
        }
        __syncthreads();
    }
    #pragma unroll
    for (int i = 0; i < 4; i++)
        #pragma unroll
        for (int j = 0; j < 4; j++)
            Cout[(size_t)(m0 + ty*4 + i)*O + o0 + tx*4 + j] = acc[i][j];
}

__global__ void k_zero(float* a, float* b) { int t = threadIdx.x; a[t] = 0.f; b[t] = 0.f; }

// h[b,n,k,o] = p[b,idx[b,n,k],o] + q[b,n,o]; emit max_k h and per-channel sums
__global__ void k_gather(const float* __restrict__ p, const float* __restrict__ q,
                         const int* __restrict__ idx, float* __restrict__ hmax,
                         float* __restrict__ sum, float* __restrict__ sumsq, int O) {
    int o  = threadIdx.x;
    int r0 = blockIdx.x*32;
    int b  = r0 >> 10;
    __shared__ int sidx[32*KNN];
    for (int i = o; i < 32*KNN; i += blockDim.x) sidx[i] = idx[(size_t)r0*KNN + i];
    __syncthreads();
    const float* pb = p + (size_t)b*NN*O;
    float s = 0.f, s2 = 0.f;
    for (int n = 0; n < 32; n++) {
        int row = r0 + n;
        float cq = q[(size_t)row*O + o];
        float mx = -INFINITY;
        #pragma unroll
        for (int k = 0; k < KNN; k++) {
            float v = pb[(size_t)sidx[n*KNN + k]*O + o];
            mx = fmaxf(mx, v);
            float h = v + cq;
            s += h; s2 += h*h;
        }
        hmax[(size_t)row*O + o] = mx + cq;
    }
    atomicAdd(&sum[o], s);
    atomicAdd(&sumsq[o], s2);
}

__global__ void k_bn(const float* __restrict__ hmax, const float* __restrict__ sum,
                     const float* __restrict__ sumsq,
                     const float* __restrict__ gamma, const float* __restrict__ beta,
                     float* __restrict__ out, int O, int os, float invCnt) {
    int e = blockIdx.x*blockDim.x + threadIdx.x;
    int row = e / O, o = e - row*O;
    float mean = sum[o]*invCnt;
    float var  = sumsq[o]*invCnt - mean*mean;
    float hn = (hmax[e] - mean)*rsqrtf(var + EPS)*gamma[o] + beta[o];
    out[(size_t)row*os + o] = hn >= 0.f ? hn : NEG_SLOPE*hn;
}

__global__ void k_reduce5(const float* __restrict__ h, float* __restrict__ bmax,
                          float* __restrict__ sum, float* __restrict__ sumsq) {
    int b = blockIdx.x;
    int o = blockIdx.y*256 + threadIdx.x;
    const float* hb = h + (size_t)b*NN*1024;
    float mx = -INFINITY, s = 0.f, s2 = 0.f;
    for (int n = 0; n < NN; n++) {
        float v = hb[(size_t)n*1024 + o];
        mx = fmaxf(mx, v); s += v; s2 += v*v;
    }
    bmax[b*1024 + o] = mx;
    atomicAdd(&sum[o], s);
    atomicAdd(&sumsq[o], s2);
}

__global__ void k_final(const float* __restrict__ bmax, const float* __restrict__ sum,
                        const float* __restrict__ sumsq,
                        const float* __restrict__ gamma, const float* __restrict__ beta,
                        float* __restrict__ out) {
    int e = blockIdx.x*blockDim.x + threadIdx.x;   // 32768
    int o = e & 1023;
    float invCnt = 1.f/32768.f;
    float mean = sum[o]*invCnt;
    float var  = sumsq[o]*invCnt - mean*mean;
    float hn = (bmax[e] - mean)*rsqrtf(var + EPS)*gamma[o] + beta[o];
    out[e] = hn >= 0.f ? hn : NEG_SLOPE*hn;
}

// ---------------- host driver ----------------

static void edge_layer(const float* F, int fs, int C, int O,
                       const float* W, const float* ga, const float* be,
                       float* pd, int* idx, float* p, float* q, float* hmax,
                       float* wq, float* xx, float* sum, float* sumsq,
                       float* catOut) {
    k_xx  <<<RTOT/256, 256>>>(F, fs, C, xx);
    k_pair<<<dim3(32,32,32), dim3(32,32)>>>(F, fs, C, xx, pd);
    k_topk<<<RTOT, 256>>>(pd, idx);
    k_wq  <<<(O*C + 255)/256, 256>>>(W, C, O, wq);
    k_sgemm<<<dim3(RTOT/64, O/64), dim3(16,16)>>>(F, fs, W,  2*C, p, C, O);
    k_sgemm<<<dim3(RTOT/64, O/64), dim3(16,16)>>>(F, fs, wq, C,   q, C, O);
    k_zero<<<1, 1024>>>(sum, sumsq);
    k_gather<<<RTOT/32, O>>>(p, q, idx, hmax, sum, sumsq, O);
    k_bn<<<(RTOT*O)/256, 256>>>(hmax, sum, sumsq, ga, be, catOut, O, 512,
                                1.f/((float)RTOT*KNN));
}

extern "C" void kernel_launch(void* const* d_in, const int* in_sizes, int n_in,
                              void* d_out, int out_size) {
    const float* x = (const float*)d_in[0];
    const float* W[5]; const float* ga[5]; const float* be[5];
    for (int i = 0; i < 5; i++) {
        W[i]  = (const float*)d_in[1 + 3*i];
        ga[i] = (const float*)d_in[2 + 3*i];
        be[i] = (const float*)d_in[3 + 3*i];
    }

    float *pd, *p, *q, *hmax, *cat, *wq, *xx, *sum, *sumsq, *bmax;
    int *idx;
    cudaGetSymbolAddress((void**)&pd,    g_pd);
    cudaGetSymbolAddress((void**)&idx,   g_idx);
    cudaGetSymbolAddress((void**)&p,     g_p);
    cudaGetSymbolAddress((void**)&q,     g_q);
    cudaGetSymbolAddress((void**)&hmax,  g_hmax);
    cudaGetSymbolAddress((void**)&cat,   g_cat);
    cudaGetSymbolAddress((void**)&wq,    g_wq);
    cudaGetSymbolAddress((void**)&xx,    g_xx);
    cudaGetSymbolAddress((void**)&sum,   g_sum);
    cudaGetSymbolAddress((void**)&sumsq, g_sumsq);
    cudaGetSymbolAddress((void**)&bmax,  g_bmax);

    // EdgeConv 1..4, outputs concatenated into g_cat slices
    edge_layer(x,        3,   3,   64,  W[0], ga[0], be[0], pd, idx, p, q, hmax, wq, xx, sum, sumsq, cat + 0);
    edge_layer(cat+0,    512, 64,  64,  W[1], ga[1], be[1], pd, idx, p, q, hmax, wq, xx, sum, sumsq, cat + 64);
    edge_layer(cat+64,   512, 64,  128, W[2], ga[2], be[2], pd, idx, p, q, hmax, wq, xx, sum, sumsq, cat + 128);
    edge_layer(cat+128,  512, 128, 256, W[3], ga[3], be[3], pd, idx, p, q, hmax, wq, xx, sum, sumsq, cat + 256);

    // layer 5: h = cat @ W5^T (into g_pd), BN over (B,N), lrelu, max over N
    k_sgemm<<<dim3(RTOT/64, 1024/64), dim3(16,16)>>>(cat, 512, W[4], 512, pd, 512, 1024);
    k_zero<<<1, 1024>>>(sum, sumsq);
    k_reduce5<<<dim3(BB, 4), 256>>>(pd, bmax, sum, sumsq);
    k_final<<<RTOT/256, 256>>>(bmax, sum, sumsq, ga[4], be[4], (float*)d_out);
}

// round 2
// speedup vs baseline: 2.7140x; 2.7140x over previous
#include <cuda_runtime.h>
#include <math.h>

#define BB 32
#define NN 1024
#define KNN 20
#define RTOT (BB*NN)          // 32768 rows
#define NEG_SLOPE 0.2f
#define EPS 1e-5f

// ---------------- static scratch (allocation-free rule) ----------------
__device__ __align__(256) float g_pd[(size_t)BB*NN*NN];     // 128 MB
__device__ __align__(256) int   g_idx[(size_t)RTOT*KNN];
__device__ __align__(256) float g_p[(size_t)RTOT*256];
__device__ __align__(256) float g_q[(size_t)RTOT*256];
__device__ __align__(256) float g_hmax[(size_t)RTOT*256];
__device__ __align__(256) float g_cat[(size_t)RTOT*512];
__device__ __align__(256) float g_wq[1024*512];
__device__ __align__(256) float g_xx[RTOT];
__device__ __align__(256) float g_sum[1024];
__device__ __align__(256) float g_sumsq[1024];
__device__ __align__(256) float g_bmax[RTOT];

// ---------------- kernels ----------------

__global__ void k_xx(const float* __restrict__ F, int fs, int C, float* __restrict__ xx) {
    int r = blockIdx.x*blockDim.x + threadIdx.x;
    if (r >= RTOT) return;
    const float* f = F + (size_t)r*fs;
    float s = 0.f;
    for (int c = 0; c < C; c++) { float v = f[c]; s += v*v; }
    xx[r] = s;
}

// slow pairwise (layer 1 only, C=3)
__global__ void k_pair(const float* __restrict__ F, int fs, int C,
                       const float* __restrict__ xx, float* __restrict__ pd) {
    int b = blockIdx.z;
    int tx = threadIdx.x, ty = threadIdx.y;
    int n = blockIdx.y*32 + ty;
    int m = blockIdx.x*32 + tx;
    __shared__ float As[32][33], Bs[32][33];
    const float* Fb = F + (size_t)b*NN*fs;
    float acc = 0.f;
    for (int c0 = 0; c0 < C; c0 += 32) {
        int c = c0 + tx;
        As[ty][tx] = (c < C) ? Fb[(size_t)(blockIdx.y*32+ty)*fs + c] : 0.f;
        Bs[ty][tx] = (c < C) ? Fb[(size_t)(blockIdx.x*32+ty)*fs + c] : 0.f;
        __syncthreads();
        #pragma unroll
        for (int cc = 0; cc < 32; cc++) acc += As[ty][cc]*Bs[tx][cc];
        __syncthreads();
    }
    pd[(size_t)b*NN*NN + (size_t)n*NN + m] = 2.f*acc - xx[b*NN + n] - xx[b*NN + m];
}

// fast pairwise GEMM: pd[b,n,m] = 2<F_n,F_m> - xx_n - xx_m  (Kdim % 16 == 0)
__global__ void k_pair_f(const float* __restrict__ F, int fs, int Kdim,
                         const float* __restrict__ xx, float* __restrict__ pd) {
    __shared__ float As[16][132];
    __shared__ float Ws[16][68];
    int b = blockIdx.z;
    const float* Fb = F + (size_t)b*NN*fs;
    const float* xb = xx + b*NN;
    int tid = threadIdx.x;
    int tx = tid & 15, ty = tid >> 4;
    int n0 = blockIdx.x*128, m0 = blockIdx.y*64;
    int r0 = tid >> 2, kc = (tid & 3)*4;
    const float* Ar0 = Fb + (size_t)(n0 + r0)*fs + kc;
    const float* Ar1 = Fb + (size_t)(n0 + 64 + r0)*fs + kc;
    const float* Wr  = Fb + (size_t)(m0 + r0)*fs + kc;
    float acc[8][4];
    #pragma unroll
    for (int i = 0; i < 8; i++)
        #pragma unroll
        for (int j = 0; j < 4; j++) acc[i][j] = 0.f;

    for (int k0 = 0; k0 < Kdim; k0 += 16) {
        float4 a0 = *(const float4*)(Ar0 + k0);
        float4 a1 = *(const float4*)(Ar1 + k0);
        float4 w0 = *(const float4*)(Wr  + k0);
        As[kc+0][r0] = a0.x; As[kc+1][r0] = a0.y; As[kc+2][r0] = a0.z; As[kc+3][r0] = a0.w;
        As[kc+0][64+r0] = a1.x; As[kc+1][64+r0] = a1.y; As[kc+2][64+r0] = a1.z; As[kc+3][64+r0] = a1.w;
        Ws[kc+0][r0] = w0.x; Ws[kc+1][r0] = w0.y; Ws[kc+2][r0] = w0.z; Ws[kc+3][r0] = w0.w;
        __syncthreads();
        #pragma unroll
        for (int kk = 0; kk < 16; kk++) {
            float4 av0 = *(const float4*)&As[kk][ty*8];
            float4 av1 = *(const float4*)&As[kk][ty*8+4];
            float4 bv  = *(const float4*)&Ws[kk][tx*4];
            float a[8] = {av0.x,av0.y,av0.z,av0.w,av1.x,av1.y,av1.z,av1.w};
            float bb[4] = {bv.x,bv.y,bv.z,bv.w};
            #pragma unroll
            for (int i = 0; i < 8; i++)
                #pragma unroll
                for (int j = 0; j < 4; j++) acc[i][j] = fmaf(a[i], bb[j], acc[i][j]);
        }
        __syncthreads();
    }
    float xm[4];
    #pragma unroll
    for (int j = 0; j < 4; j++) xm[j] = xb[m0 + tx*4 + j];
    float* prow = pd + (size_t)b*NN*NN;
    #pragma unroll
    for (int i = 0; i < 8; i++) {
        int n = n0 + ty*8 + i;
        float xn = xb[n];
        float4 o = make_float4(2.f*acc[i][0] - xn - xm[0],
                               2.f*acc[i][1] - xn - xm[1],
                               2.f*acc[i][2] - xn - xm[2],
                               2.f*acc[i][3] - xn - xm[3]);
        *(float4*)(prow + (size_t)n*NN + m0 + tx*4) = o;
    }
}

// warp-per-row top-20 (largest value, tie -> lower index)
__global__ void k_topk_w(const float* __restrict__ pd, int* __restrict__ idx) {
    int warp = threadIdx.x >> 5;
    int lane = threadIdx.x & 31;
    int row = blockIdx.x*8 + warp;
    const float* prow = pd + (size_t)row*NN;
    float vals[32];
    #pragma unroll
    for (int j = 0; j < 32; j++) vals[j] = prow[j*32 + lane];
    unsigned rm = 0;
    float bv = vals[0]; int bslot = 0;
    #pragma unroll
    for (int j = 1; j < 32; j++) { float v = vals[j]; if (v > bv) { bv = v; bslot = j; } }
    int* orow = idx + (size_t)row*KNN;
    for (int it = 0; it < KNN; it++) {
        float cv = bv;
        int ci = (bslot >= 0) ? (bslot*32 + lane) : 0x7fffffff;
        if (bslot < 0) cv = -INFINITY;
        #pragma unroll
        for (int s = 16; s > 0; s >>= 1) {
            float ov = __shfl_xor_sync(0xffffffffu, cv, s);
            int   oi = __shfl_xor_sync(0xffffffffu, ci, s);
            if (ov > cv || (ov == cv && oi < ci)) { cv = ov; ci = oi; }
        }
        if (lane == 0) orow[it] = ci;
        if ((ci & 31) == lane) {
            rm |= 1u << (ci >> 5);
            bv = -INFINITY; bslot = -1;
            #pragma unroll
            for (int j = 0; j < 32; j++) {
                if (!((rm >> j) & 1u)) {
                    float v = vals[j];
                    if (v > bv) { bv = v; bslot = j; }
                }
            }
        }
    }
}

__global__ void k_wq(const float* __restrict__ W, int C, int O, float* __restrict__ wq) {
    int i = blockIdx.x*blockDim.x + threadIdx.x;
    if (i >= O*C) return;
    int o = i / C, c = i - o*C;
    wq[i] = W[(size_t)o*2*C + C + c] - W[(size_t)o*2*C + c];
}

// generic slow sgemm (layer 1, K=3)
__global__ void k_sgemm(const float* __restrict__ A, int lda,
                        const float* __restrict__ Bw, int ldb,
                        float* __restrict__ Cout, int Kdim, int O) {
    __shared__ float As[16][65], Ws[16][65];
    int tx = threadIdx.x, ty = threadIdx.y;
    int tid = ty*16 + tx;
    int m0 = blockIdx.x*64, o0 = blockIdx.y*64;
    float acc[4][4];
    #pragma unroll
    for (int i = 0; i < 4; i++)
        #pragma unroll
        for (int j = 0; j < 4; j++) acc[i][j] = 0.f;
    for (int k0 = 0; k0 < Kdim; k0 += 16) {
        #pragma unroll
        for (int r = 0; r < 4; r++) {
            int i  = tid + r*256;
            int kk = i & 15, mm = i >> 4;
            As[kk][mm] = (k0+kk < Kdim) ? A[(size_t)(m0+mm)*lda + k0+kk] : 0.f;
            Ws[kk][mm] = (k0+kk < Kdim) ? Bw[(size_t)(o0+mm)*ldb + k0+kk] : 0.f;
        }
        __syncthreads();
        #pragma unroll
        for (int kk = 0; kk < 16; kk++) {
            float a[4], bfr[4];
            #pragma unroll
            for (int i = 0; i < 4; i++) a[i] = As[kk][ty*4 + i];
            #pragma unroll
            for (int j = 0; j < 4; j++) bfr[j] = Ws[kk][tx*4 + j];
            #pragma unroll
            for (int i = 0; i < 4; i++)
                #pragma unroll
                for (int j = 0; j < 4; j++) acc[i][j] += a[i]*bfr[j];
        }
        __syncthreads();
    }
    #pragma unroll
    for (int i = 0; i < 4; i++)
        #pragma unroll
        for (int j = 0; j < 4; j++)
            Cout[(size_t)(m0 + ty*4 + i)*O + o0 + tx*4 + j] = acc[i][j];
}

// fast sgemm: Cout[m,o] = sum_k A[m,k]*Bw[o,k]; Kdim%16==0, lda/ldb/ldc%4==0
__global__ void k_sgemm_f(const float* __restrict__ A, int lda,
                          const float* __restrict__ Bw, int ldb,
                          float* __restrict__ Cout, int ldc, int Kdim) {
    __shared__ float As[16][132];
    __shared__ float Ws[16][68];
    int tid = threadIdx.x;
    int tx = tid & 15, ty = tid >> 4;
    int m0 = blockIdx.x*128, o0 = blockIdx.y*64;
    int r0 = tid >> 2, kc = (tid & 3)*4;
    const float* Ar0 = A  + (size_t)(m0 + r0)*lda + kc;
    const float* Ar1 = A  + (size_t)(m0 + 64 + r0)*lda + kc;
    const float* Wr  = Bw + (size_t)(o0 + r0)*ldb + kc;
    float acc[8][4];
    #pragma unroll
    for (int i = 0; i < 8; i++)
        #pragma unroll
        for (int j = 0; j < 4; j++) acc[i][j] = 0.f;

    for (int k0 = 0; k0 < Kdim; k0 += 16) {
        float4 a0 = *(const float4*)(Ar0 + k0);
        float4 a1 = *(const float4*)(Ar1 + k0);
        float4 w0 = *(const float4*)(Wr  + k0);
        As[kc+0][r0] = a0.x; As[kc+1][r0] = a0.y; As[kc+2][r0] = a0.z; As[kc+3][r0] = a0.w;
        As[kc+0][64+r0] = a1.x; As[kc+1][64+r0] = a1.y; As[kc+2][64+r0] = a1.z; As[kc+3][64+r0] = a1.w;
        Ws[kc+0][r0] = w0.x; Ws[kc+1][r0] = w0.y; Ws[kc+2][r0] = w0.z; Ws[kc+3][r0] = w0.w;
        __syncthreads();
        #pragma unroll
        for (int kk = 0; kk < 16; kk++) {
            float4 av0 = *(const float4*)&As[kk][ty*8];
            float4 av1 = *(const float4*)&As[kk][ty*8+4];
            float4 bv  = *(const float4*)&Ws[kk][tx*4];
            float a[8] = {av0.x,av0.y,av0.z,av0.w,av1.x,av1.y,av1.z,av1.w};
            float bb[4] = {bv.x,bv.y,bv.z,bv.w};
            #pragma unroll
            for (int i = 0; i < 8; i++)
                #pragma unroll
                for (int j = 0; j < 4; j++) acc[i][j] = fmaf(a[i], bb[j], acc[i][j]);
        }
        __syncthreads();
    }
    #pragma unroll
    for (int i = 0; i < 8; i++) {
        float4 o = make_float4(acc[i][0], acc[i][1], acc[i][2], acc[i][3]);
        *(float4*)(Cout + (size_t)(m0 + ty*8 + i)*ldc + o0 + tx*4) = o;
    }
}

__global__ void k_zero(float* a, float* b) { int t = threadIdx.x; a[t] = 0.f; b[t] = 0.f; }

__global__ void k_gather(const float* __restrict__ p, const float* __restrict__ q,
                         const int* __restrict__ idx, float* __restrict__ hmax,
                         float* __restrict__ sum, float* __restrict__ sumsq, int O) {
    int o  = threadIdx.x;
    int r0 = blockIdx.x*32;
    int b  = r0 >> 10;
    __shared__ int sidx[32*KNN];
    for (int i = o; i < 32*KNN; i += blockDim.x) sidx[i] = idx[(size_t)r0*KNN + i];
    __syncthreads();
    const float* pb = p + (size_t)b*NN*O;
    float s = 0.f, s2 = 0.f;
    for (int n = 0; n < 32; n++) {
        int row = r0 + n;
        float cq = q[(size_t)row*O + o];
        float mx = -INFINITY;
        #pragma unroll
        for (int k = 0; k < KNN; k++) {
            float v = pb[(size_t)sidx[n*KNN + k]*O + o];
            mx = fmaxf(mx, v);
            float h = v + cq;
            s += h; s2 += h*h;
        }
        hmax[(size_t)row*O + o] = mx + cq;
    }
    atomicAdd(&sum[o], s);
    atomicAdd(&sumsq[o], s2);
}

__global__ void k_bn(const float* __restrict__ hmax, const float* __restrict__ sum,
                     const float* __restrict__ sumsq,
                     const float* __restrict__ gamma, const float* __restrict__ beta,
                     float* __restrict__ out, int O, int os, float invCnt) {
    int e = blockIdx.x*blockDim.x + threadIdx.x;
    int row = e / O, o = e - row*O;
    float mean = sum[o]*invCnt;
    float var  = sumsq[o]*invCnt - mean*mean;
    float hn = (hmax[e] - mean)*rsqrtf(var + EPS)*gamma[o] + beta[o];
    out[(size_t)row*os + o] = hn >= 0.f ? hn : NEG_SLOPE*hn;
}

__global__ void k_reduce5(const float* __restrict__ h, float* __restrict__ bmax,
                          float* __restrict__ sum, float* __restrict__ sumsq) {
    int b = blockIdx.x;
    int o = blockIdx.y*256 + threadIdx.x;
    const float* hb = h + (size_t)b*NN*1024;
    float mx = -INFINITY, s = 0.f, s2 = 0.f;
    for (int n = 0; n < NN; n++) {
        float v = hb[(size_t)n*1024 + o];
        mx = fmaxf(mx, v); s += v; s2 += v*v;
    }
    bmax[b*1024 + o] = mx;
    atomicAdd(&sum[o], s);
    atomicAdd(&sumsq[o], s2);
}

__global__ void k_final(const float* __restrict__ bmax, const float* __restrict__ sum,
                        const float* __restrict__ sumsq,
                        const float* __restrict__ gamma, const float* __restrict__ beta,
                        float* __restrict__ out) {
    int e = blockIdx.x*blockDim.x + threadIdx.x;   // 32768
    int o = e & 1023;
    float invCnt = 1.f/32768.f;
    float mean = sum[o]*invCnt;
    float var  = sumsq[o]*invCnt - mean*mean;
    float hn = (bmax[e] - mean)*rsqrtf(var + EPS)*gamma[o] + beta[o];
    out[e] = hn >= 0.f ? hn : NEG_SLOPE*hn;
}

// ---------------- host driver ----------------

static void edge_layer(const float* F, int fs, int C, int O,
                       const float* W, const float* ga, const float* be,
                       float* pd, int* idx, float* p, float* q, float* hmax,
                       float* wq, float* xx, float* sum, float* sumsq,
                       float* catOut, bool fast) {
    k_xx<<<RTOT/256, 256>>>(F, fs, C, xx);
    if (fast) k_pair_f<<<dim3(8, 16, 32), 256>>>(F, fs, C, xx, pd);
    else      k_pair<<<dim3(32, 32, 32), dim3(32, 32)>>>(F, fs, C, xx, pd);
    k_topk_w<<<RTOT/8, 256>>>(pd, idx);
    k_wq<<<(O*C + 255)/256, 256>>>(W, C, O, wq);
    if (fast) {
        k_sgemm_f<<<dim3(RTOT/128, O/64), 256>>>(F, fs, W,  2*C, p, O, C);
        k_sgemm_f<<<dim3(RTOT/128, O/64), 256>>>(F, fs, wq, C,   q, O, C);
    } else {
        k_sgemm<<<dim3(RTOT/64, O/64), dim3(16,16)>>>(F, fs, W,  2*C, p, C, O);
        k_sgemm<<<dim3(RTOT/64, O/64), dim3(16,16)>>>(F, fs, wq, C,   q, C, O);
    }
    k_zero<<<1, 1024>>>(sum, sumsq);
    k_gather<<<RTOT/32, O>>>(p, q, idx, hmax, sum, sumsq, O);
    k_bn<<<(RTOT*O)/256, 256>>>(hmax, sum, sumsq, ga, be, catOut, O, 512,
                                1.f/((float)RTOT*KNN));
}

extern "C" void kernel_launch(void* const* d_in, const int* in_sizes, int n_in,
                              void* d_out, int out_size) {
    const float* x = (const float*)d_in[0];
    const float* W[5]; const float* ga[5]; const float* be[5];
    for (int i = 0; i < 5; i++) {
        W[i]  = (const float*)d_in[1 + 3*i];
        ga[i] = (const float*)d_in[2 + 3*i];
        be[i] = (const float*)d_in[3 + 3*i];
    }

    float *pd, *p, *q, *hmax, *cat, *wq, *xx, *sum, *sumsq, *bmax;
    int *idx;
    cudaGetSymbolAddress((void**)&pd,    g_pd);
    cudaGetSymbolAddress((void**)&idx,   g_idx);
    cudaGetSymbolAddress((void**)&p,     g_p);
    cudaGetSymbolAddress((void**)&q,     g_q);
    cudaGetSymbolAddress((void**)&hmax,  g_hmax);
    cudaGetSymbolAddress((void**)&cat,   g_cat);
    cudaGetSymbolAddress((void**)&wq,    g_wq);
    cudaGetSymbolAddress((void**)&xx,    g_xx);
    cudaGetSymbolAddress((void**)&sum,   g_sum);
    cudaGetSymbolAddress((void**)&sumsq, g_sumsq);
    cudaGetSymbolAddress((void**)&bmax,  g_bmax);

    // EdgeConv 1..4, outputs concatenated into g_cat slices
    edge_layer(x,       3,   3,   64,  W[0], ga[0], be[0], pd, idx, p, q, hmax, wq, xx, sum, sumsq, cat + 0,   false);
    edge_layer(cat+0,   512, 64,  64,  W[1], ga[1], be[1], pd, idx, p, q, hmax, wq, xx, sum, sumsq, cat + 64,  true);
    edge_layer(cat+64,  512, 64,  128, W[2], ga[2], be[2], pd, idx, p, q, hmax, wq, xx, sum, sumsq, cat + 128, true);
    edge_layer(cat+128, 512, 128, 256, W[3], ga[3], be[3], pd, idx, p, q, hmax, wq, xx, sum, sumsq, cat + 256, true);

    // layer 5: h = cat @ W5^T (into g_pd), BN over (B,N), lrelu, max over N
    k_sgemm_f<<<dim3(RTOT/128, 1024/64), 256>>>(cat, 512, W[4], 512, pd, 1024, 512);
    k_zero<<<1, 1024>>>(sum, sumsq);
    k_reduce5<<<dim3(BB, 4), 256>>>(pd, bmax, sum, sumsq);
    k_final<<<RTOT/256, 256>>>(bmax, sum, sumsq, ga[4], be[4], (float*)d_out);
}

// round 3
// speedup vs baseline: 3.1392x; 1.1567x over previous
#include <cuda_runtime.h>
#include <math.h>

#define BB 32
#define NN 1024
#define KNN 20
#define RTOT (BB*NN)          // 32768 rows
#define NEG_SLOPE 0.2f
#define EPS 1e-5f

// ---------------- static scratch (allocation-free rule) ----------------
__device__ __align__(256) float g_pd[(size_t)BB*NN*NN];     // 128 MB
__device__ __align__(256) int   g_idx[(size_t)RTOT*KNN];
__device__ __align__(256) float g_p[(size_t)RTOT*256];
__device__ __align__(256) float g_q[(size_t)RTOT*256];
__device__ __align__(256) float g_hmax[(size_t)RTOT*256];
__device__ __align__(256) float g_cat[(size_t)RTOT*512];
__device__ __align__(256) float g_wq[1024*512];
__device__ __align__(256) float g_xx[RTOT];
__device__ __align__(256) float g_sum[1024];
__device__ __align__(256) float g_sumsq[1024];
__device__ __align__(256) float g_bmax[RTOT];

// ---------------- f32x2 helpers ----------------
__device__ __forceinline__ void fma2(unsigned long long &acc,
                                     unsigned long long a, unsigned long long b) {
    asm("fma.rn.f32x2 %0, %1, %2, %0;" : "+l"(acc) : "l"(a), "l"(b));
}
__device__ __forceinline__ unsigned long long dup2(float v) {
    unsigned long long r;
    asm("mov.b64 %0, {%1, %1};" : "=l"(r) : "f"(v));
    return r;
}
__device__ __forceinline__ float2 unpack2(unsigned long long v) {
    float lo, hi;
    asm("mov.b64 {%0, %1}, %2;" : "=f"(lo), "=f"(hi) : "l"(v));
    return make_float2(lo, hi);
}

// ---------------- warp top-20 over 32x32 register tile ----------------
__device__ __forceinline__ void warp_top20(float (&vals)[32], int lane, int* orow) {
    unsigned rm = 0;
    float bv = vals[0]; int bslot = 0;
    #pragma unroll
    for (int j = 1; j < 32; j++) { float v = vals[j]; if (v > bv) { bv = v; bslot = j; } }
    for (int it = 0; it < KNN; it++) {
        float cv = bv;
        int ci = (bslot >= 0) ? (bslot*32 + lane) : 0x7fffffff;
        if (bslot < 0) cv = -INFINITY;
        #pragma unroll
        for (int s = 16; s > 0; s >>= 1) {
            float ov = __shfl_xor_sync(0xffffffffu, cv, s);
            int   oi = __shfl_xor_sync(0xffffffffu, ci, s);
            if (ov > cv || (ov == cv && oi < ci)) { cv = ov; ci = oi; }
        }
        if (lane == 0) orow[it] = ci;
        if ((ci & 31) == lane) {
            rm |= 1u << (ci >> 5);
            bv = -INFINITY; bslot = -1;
            #pragma unroll
            for (int j = 0; j < 32; j++) {
                if (!((rm >> j) & 1u)) {
                    float v = vals[j];
                    if (v > bv) { bv = v; bslot = j; }
                }
            }
        }
    }
}

// ---------------- kernels ----------------

__global__ void k_xx(const float* __restrict__ F, int fs, int C, float* __restrict__ xx) {
    int r = blockIdx.x*blockDim.x + threadIdx.x;
    if (r >= RTOT) return;
    const float* f = F + (size_t)r*fs;
    float s = 0.f;
    for (int c = 0; c < C; c++) { float v = f[c]; s += v*v; }
    xx[r] = s;
}

// fused layer-1 KNN: C=3, distances computed on the fly from shared x
__global__ void k_knn3(const float* __restrict__ x, int* __restrict__ idx) {
    __shared__ float sx[NN], sy[NN], sz[NN];
    int b = blockIdx.y;
    const float* xb = x + (size_t)b*NN*3;
    int tid = threadIdx.x;
    for (int i = tid; i < NN; i += 256) {
        sx[i] = xb[i*3+0]; sy[i] = xb[i*3+1]; sz[i] = xb[i*3+2];
    }
    __syncthreads();
    int warp = tid >> 5, lane = tid & 31;
    int n = blockIdx.x*8 + warp;
    float xnx = sx[n], xny = sy[n], xnz = sz[n];
    float xxn = xnx*xnx; xxn += xny*xny; xxn += xnz*xnz;
    float vals[32];
    #pragma unroll
    for (int j = 0; j < 32; j++) {
        int m = j*32 + lane;
        float mx = sx[m], my = sy[m], mz = sz[m];
        float inner = xnx*mx; inner += xny*my; inner += xnz*mz;
        float xxm = mx*mx; xxm += my*my; xxm += mz*mz;
        vals[j] = 2.f*inner - xxn - xxm;
    }
    warp_top20(vals, lane, idx + (size_t)(b*NN + n)*KNN);
}

// fast pairwise GEMM (FFMA2): pd[b,n,m] = 2<F_n,F_m> - xx_n - xx_m  (Kdim%16==0)
__global__ void k_pair_f(const float* __restrict__ F, int fs, int Kdim,
                         const float* __restrict__ xx, float* __restrict__ pd) {
    __shared__ float As[16][132];
    __shared__ float Ws[16][68];
    int b = blockIdx.z;
    const float* Fb = F + (size_t)b*NN*fs;
    const float* xb = xx + b*NN;
    int tid = threadIdx.x;
    int tx = tid & 15, ty = tid >> 4;
    int n0 = blockIdx.x*128, m0 = blockIdx.y*64;
    int r0 = tid >> 2, kc = (tid & 3)*4;
    const float* Ar0 = Fb + (size_t)(n0 + r0)*fs + kc;
    const float* Ar1 = Fb + (size_t)(n0 + 64 + r0)*fs + kc;
    const float* Wr  = Fb + (size_t)(m0 + r0)*fs + kc;
    unsigned long long acc[4][4];
    #pragma unroll
    for (int i = 0; i < 4; i++)
        #pragma unroll
        for (int j = 0; j < 4; j++) acc[i][j] = 0ULL;

    for (int k0 = 0; k0 < Kdim; k0 += 16) {
        float4 a0 = *(const float4*)(Ar0 + k0);
        float4 a1 = *(const float4*)(Ar1 + k0);
        float4 w0 = *(const float4*)(Wr  + k0);
        As[kc+0][r0] = a0.x; As[kc+1][r0] = a0.y; As[kc+2][r0] = a0.z; As[kc+3][r0] = a0.w;
        As[kc+0][64+r0] = a1.x; As[kc+1][64+r0] = a1.y; As[kc+2][64+r0] = a1.z; As[kc+3][64+r0] = a1.w;
        Ws[kc+0][r0] = w0.x; Ws[kc+1][r0] = w0.y; Ws[kc+2][r0] = w0.z; Ws[kc+3][r0] = w0.w;
        __syncthreads();
        #pragma unroll
        for (int kk = 0; kk < 16; kk++) {
            ulonglong2 aLo = *(const ulonglong2*)&As[kk][ty*8];
            ulonglong2 aHi = *(const ulonglong2*)&As[kk][ty*8+4];
            float4 bv = *(const float4*)&Ws[kk][tx*4];
            unsigned long long ap[4] = {aLo.x, aLo.y, aHi.x, aHi.y};
            unsigned long long bp[4] = {dup2(bv.x), dup2(bv.y), dup2(bv.z), dup2(bv.w)};
            #pragma unroll
            for (int i = 0; i < 4; i++)
                #pragma unroll
                for (int j = 0; j < 4; j++) fma2(acc[i][j], ap[i], bp[j]);
        }
        __syncthreads();
    }
    float xm[4];
    #pragma unroll
    for (int j = 0; j < 4; j++) xm[j] = xb[m0 + tx*4 + j];
    float* prow = pd + (size_t)b*NN*NN;
    #pragma unroll
    for (int ip = 0; ip < 4; ip++) {
        float2 c0 = unpack2(acc[ip][0]);
        float2 c1 = unpack2(acc[ip][1]);
        float2 c2 = unpack2(acc[ip][2]);
        float2 c3 = unpack2(acc[ip][3]);
        int n = n0 + ty*8 + ip*2;
        float xn0 = xb[n], xn1 = xb[n+1];
        *(float4*)(prow + (size_t)n*NN + m0 + tx*4) =
            make_float4(2.f*c0.x - xn0 - xm[0], 2.f*c1.x - xn0 - xm[1],
                        2.f*c2.x - xn0 - xm[2], 2.f*c3.x - xn0 - xm[3]);
        *(float4*)(prow + (size_t)(n+1)*NN + m0 + tx*4) =
            make_float4(2.f*c0.y - xn1 - xm[0], 2.f*c1.y - xn1 - xm[1],
                        2.f*c2.y - xn1 - xm[2], 2.f*c3.y - xn1 - xm[3]);
    }
}

// warp-per-row top-20 from precomputed pd
__global__ void k_topk_w(const float* __restrict__ pd, int* __restrict__ idx) {
    int warp = threadIdx.x >> 5;
    int lane = threadIdx.x & 31;
    int row = blockIdx.x*8 + warp;
    const float* prow = pd + (size_t)row*NN;
    float vals[32];
    #pragma unroll
    for (int j = 0; j < 32; j++) vals[j] = prow[j*32 + lane];
    warp_top20(vals, lane, idx + (size_t)row*KNN);
}

__global__ void k_wq(const float* __restrict__ W, int C, int O, float* __restrict__ wq) {
    int i = blockIdx.x*blockDim.x + threadIdx.x;
    if (i >= O*C) return;
    int o = i / C, c = i - o*C;
    wq[i] = W[(size_t)o*2*C + C + c] - W[(size_t)o*2*C + c];
}

// generic slow sgemm (layer 1, K=3)
__global__ void k_sgemm(const float* __restrict__ A, int lda,
                        const float* __restrict__ Bw, int ldb,
                        float* __restrict__ Cout, int Kdim, int O) {
    __shared__ float As[16][65], Ws[16][65];
    int tx = threadIdx.x, ty = threadIdx.y;
    int tid = ty*16 + tx;
    int m0 = blockIdx.x*64, o0 = blockIdx.y*64;
    float acc[4][4];
    #pragma unroll
    for (int i = 0; i < 4; i++)
        #pragma unroll
        for (int j = 0; j < 4; j++) acc[i][j] = 0.f;
    for (int k0 = 0; k0 < Kdim; k0 += 16) {
        #pragma unroll
        for (int r = 0; r < 4; r++) {
            int i  = tid + r*256;
            int kk = i & 15, mm = i >> 4;
            As[kk][mm] = (k0+kk < Kdim) ? A[(size_t)(m0+mm)*lda + k0+kk] : 0.f;
            Ws[kk][mm] = (k0+kk < Kdim) ? Bw[(size_t)(o0+mm)*ldb + k0+kk] : 0.f;
        }
        __syncthreads();
        #pragma unroll
        for (int kk = 0; kk < 16; kk++) {
            float a[4], bfr[4];
            #pragma unroll
            for (int i = 0; i < 4; i++) a[i] = As[kk][ty*4 + i];
            #pragma unroll
            for (int j = 0; j < 4; j++) bfr[j] = Ws[kk][tx*4 + j];
            #pragma unroll
            for (int i = 0; i < 4; i++)
                #pragma unroll
                for (int j = 0; j < 4; j++) acc[i][j] += a[i]*bfr[j];
        }
        __syncthreads();
    }
    #pragma unroll
    for (int i = 0; i < 4; i++)
        #pragma unroll
        for (int j = 0; j < 4; j++)
            Cout[(size_t)(m0 + ty*4 + i)*O + o0 + tx*4 + j] = acc[i][j];
}

// fast sgemm (FFMA2): Cout[m,o] = sum_k A[m,k]*Bw[o,k]; Kdim%16==0
__global__ void k_sgemm_f(const float* __restrict__ A, int lda,
                          const float* __restrict__ Bw, int ldb,
                          float* __restrict__ Cout, int ldc, int Kdim) {
    __shared__ float As[16][132];
    __shared__ float Ws[16][68];
    int tid = threadIdx.x;
    int tx = tid & 15, ty = tid >> 4;
    int m0 = blockIdx.x*128, o0 = blockIdx.y*64;
    int r0 = tid >> 2, kc = (tid & 3)*4;
    const float* Ar0 = A  + (size_t)(m0 + r0)*lda + kc;
    const float* Ar1 = A  + (size_t)(m0 + 64 + r0)*lda + kc;
    const float* Wr  = Bw + (size_t)(o0 + r0)*ldb + kc;
    unsigned long long acc[4][4];
    #pragma unroll
    for (int i = 0; i < 4; i++)
        #pragma unroll
        for (int j = 0; j < 4; j++) acc[i][j] = 0ULL;

    for (int k0 = 0; k0 < Kdim; k0 += 16) {
        float4 a0 = *(const float4*)(Ar0 + k0);
        float4 a1 = *(const float4*)(Ar1 + k0);
        float4 w0 = *(const float4*)(Wr  + k0);
        As[kc+0][r0] = a0.x; As[kc+1][r0] = a0.y; As[kc+2][r0] = a0.z; As[kc+3][r0] = a0.w;
        As[kc+0][64+r0] = a1.x; As[kc+1][64+r0] = a1.y; As[kc+2][64+r0] = a1.z; As[kc+3][64+r0] = a1.w;
        Ws[kc+0][r0] = w0.x; Ws[kc+1][r0] = w0.y; Ws[kc+2][r0] = w0.z; Ws[kc+3][r0] = w0.w;
        __syncthreads();
        #pragma unroll
        for (int kk = 0; kk < 16; kk++) {
            ulonglong2 aLo = *(const ulonglong2*)&As[kk][ty*8];
            ulonglong2 aHi = *(const ulonglong2*)&As[kk][ty*8+4];
            float4 bv = *(const float4*)&Ws[kk][tx*4];
            unsigned long long ap[4] = {aLo.x, aLo.y, aHi.x, aHi.y};
            unsigned long long bp[4] = {dup2(bv.x), dup2(bv.y), dup2(bv.z), dup2(bv.w)};
            #pragma unroll
            for (int i = 0; i < 4; i++)
                #pragma unroll
                for (int j = 0; j < 4; j++) fma2(acc[i][j], ap[i], bp[j]);
        }
        __syncthreads();
    }
    #pragma unroll
    for (int ip = 0; ip < 4; ip++) {
        float2 c0 = unpack2(acc[ip][0]);
        float2 c1 = unpack2(acc[ip][1]);
        float2 c2 = unpack2(acc[ip][2]);
        float2 c3 = unpack2(acc[ip][3]);
        int mrow = m0 + ty*8 + ip*2;
        *(float4*)(Cout + (size_t)mrow*ldc + o0 + tx*4) =
            make_float4(c0.x, c1.x, c2.x, c3.x);
        *(float4*)(Cout + (size_t)(mrow+1)*ldc + o0 + tx*4) =
            make_float4(c0.y, c1.y, c2.y, c3.y);
    }
}

__global__ void k_zero(float* a, float* b) { int t = threadIdx.x; a[t] = 0.f; b[t] = 0.f; }

__global__ void k_gather(const float* __restrict__ p, const float* __restrict__ q,
                         const int* __restrict__ idx, float* __restrict__ hmax,
                         float* __restrict__ sum, float* __restrict__ sumsq, int O) {
    int o  = threadIdx.x;
    int r0 = blockIdx.x*32;
    int b  = r0 >> 10;
    __shared__ int sidx[32*KNN];
    for (int i = o; i < 32*KNN; i += blockDim.x) sidx[i] = idx[(size_t)r0*KNN + i];
    __syncthreads();
    const float* pb = p + (size_t)b*NN*O;
    float s = 0.f, s2 = 0.f;
    for (int n = 0; n < 32; n++) {
        int row = r0 + n;
        float cq = q[(size_t)row*O + o];
        float mx = -INFINITY;
        #pragma unroll
        for (int k = 0; k < KNN; k++) {
            float v = pb[(size_t)sidx[n*KNN + k]*O + o];
            mx = fmaxf(mx, v);
            float h = v + cq;
            s += h; s2 += h*h;
        }
        hmax[(size_t)row*O + o] = mx + cq;
    }
    atomicAdd(&sum[o], s);
    atomicAdd(&sumsq[o], s2);
}

__global__ void k_bn(const float* __restrict__ hmax, const float* __restrict__ sum,
                     const float* __restrict__ sumsq,
                     const float* __restrict__ gamma, const float* __restrict__ beta,
                     float* __restrict__ out, int O, int os, float invCnt) {
    int e = blockIdx.x*blockDim.x + threadIdx.x;
    int row = e / O, o = e - row*O;
    float mean = sum[o]*invCnt;
    float var  = sumsq[o]*invCnt - mean*mean;
    float hn = (hmax[e] - mean)*rsqrtf(var + EPS)*gamma[o] + beta[o];
    out[(size_t)row*os + o] = hn >= 0.f ? hn : NEG_SLOPE*hn;
}

__global__ void k_reduce5(const float* __restrict__ h, float* __restrict__ bmax,
                          float* __restrict__ sum, float* __restrict__ sumsq) {
    int b = blockIdx.x;
    int o = blockIdx.y*256 + threadIdx.x;
    const float* hb = h + (size_t)b*NN*1024;
    float mx = -INFINITY, s = 0.f, s2 = 0.f;
    for (int n = 0; n < NN; n++) {
        float v = hb[(size_t)n*1024 + o];
        mx = fmaxf(mx, v); s += v; s2 += v*v;
    }
    bmax[b*1024 + o] = mx;
    atomicAdd(&sum[o], s);
    atomicAdd(&sumsq[o], s2);
}

__global__ void k_final(const float* __restrict__ bmax, const float* __restrict__ sum,
                        const float* __restrict__ sumsq,
                        const float* __restrict__ gamma, const float* __restrict__ beta,
                        float* __restrict__ out) {
    int e = blockIdx.x*blockDim.x + threadIdx.x;   // 32768
    int o = e & 1023;
    float invCnt = 1.f/32768.f;
    float mean = sum[o]*invCnt;
    float var  = sumsq[o]*invCnt - mean*mean;
    float hn = (bmax[e] - mean)*rsqrtf(var + EPS)*gamma[o] + beta[o];
    out[e] = hn >= 0.f ? hn : NEG_SLOPE*hn;
}

// ---------------- host driver ----------------

static void edge_layer_fast(const float* F, int fs, int C, int O,
                            const float* W, const float* wq,
                            const float* ga, const float* be,
                            float* pd, int* idx, float* p, float* q, float* hmax,
                            float* xx, float* sum, float* sumsq, float* catOut) {
    k_xx<<<RTOT/256, 256>>>(F, fs, C, xx);
    k_pair_f<<<dim3(8, 16, 32), 256>>>(F, fs, C, xx, pd);
    k_topk_w<<<RTOT/8, 256>>>(pd, idx);
    k_sgemm_f<<<dim3(RTOT/128, O/64), 256>>>(F, fs, W,  2*C, p, O, C);
    k_sgemm_f<<<dim3(RTOT/128, O/64), 256>>>(F, fs, wq, C,   q, O, C);
    k_zero<<<1, 1024>>>(sum, sumsq);
    k_gather<<<RTOT/32, O>>>(p, q, idx, hmax, sum, sumsq, O);
    k_bn<<<(RTOT*O)/256, 256>>>(hmax, sum, sumsq, ga, be, catOut, O, 512,
                                1.f/((float)RTOT*KNN));
}

extern "C" void kernel_launch(void* const* d_in, const int* in_sizes, int n_in,
                              void* d_out, int out_size) {
    const float* x = (const float*)d_in[0];
    const float* W[5]; const float* ga[5]; const float* be[5];
    for (int i = 0; i < 5; i++) {
        W[i]  = (const float*)d_in[1 + 3*i];
        ga[i] = (const float*)d_in[2 + 3*i];
        be[i] = (const float*)d_in[3 + 3*i];
    }

    float *pd, *p, *q, *hmax, *cat, *wq, *xx, *sum, *sumsq, *bmax;
    int *idx;
    cudaGetSymbolAddress((void**)&pd,    g_pd);
    cudaGetSymbolAddress((void**)&idx,   g_idx);
    cudaGetSymbolAddress((void**)&p,     g_p);
    cudaGetSymbolAddress((void**)&q,     g_q);
    cudaGetSymbolAddress((void**)&hmax,  g_hmax);
    cudaGetSymbolAddress((void**)&cat,   g_cat);
    cudaGetSymbolAddress((void**)&wq,    g_wq);
    cudaGetSymbolAddress((void**)&xx,    g_xx);
    cudaGetSymbolAddress((void**)&sum,   g_sum);
    cudaGetSymbolAddress((void**)&sumsq, g_sumsq);
    cudaGetSymbolAddress((void**)&bmax,  g_bmax);

    // wq slices (hoisted — only depend on W inputs)
    float* wq1 = wq;                 // 64*3   = 192
    float* wq2 = wq + 4096;          // 64*64  = 4096
    float* wq3 = wq + 4096 + 4096;   // 128*64 = 8192
    float* wq4 = wq + 4096 + 4096 + 8192;  // 256*128 = 32768
    k_wq<<<(64*3   + 255)/256, 256>>>(W[0], 3,   64,  wq1);
    k_wq<<<(64*64  + 255)/256, 256>>>(W[1], 64,  64,  wq2);
    k_wq<<<(128*64 + 255)/256, 256>>>(W[2], 64,  128, wq3);
    k_wq<<<(256*128+ 255)/256, 256>>>(W[3], 128, 256, wq4);

    // ---- layer 1 (C=3): fused knn, slow tiny GEMMs ----
    k_knn3<<<dim3(128, 32), 256>>>(x, idx);
    k_sgemm<<<dim3(RTOT/64, 1), dim3(16,16)>>>(x, 3, W[0], 6, p,   3, 64);
    k_sgemm<<<dim3(RTOT/64, 1), dim3(16,16)>>>(x, 3, wq1,  3, q,   3, 64);
    k_zero<<<1, 1024>>>(sum, sumsq);
    k_gather<<<RTOT/32, 64>>>(p, q, idx, hmax, sum, sumsq, 64);
    k_bn<<<(RTOT*64)/256, 256>>>(hmax, sum, sumsq, ga[0], be[0], cat + 0, 64, 512,
                                 1.f/((float)RTOT*KNN));

    // ---- layers 2-4 ----
    edge_layer_fast(cat+0,   512, 64,  64,  W[1], wq2, ga[1], be[1],
                    pd, idx, p, q, hmax, xx, sum, sumsq, cat + 64);
    edge_layer_fast(cat+64,  512, 64,  128, W[2], wq3, ga[2], be[2],
                    pd, idx, p, q, hmax, xx, sum, sumsq, cat + 128);
    edge_layer_fast(cat+128, 512, 128, 256, W[3], wq4, ga[3], be[3],
                    pd, idx, p, q, hmax, xx, sum, sumsq, cat + 256);

    // ---- layer 5: h = cat @ W5^T (into g_pd), BN over (B,N), lrelu, max over N ----
    k_sgemm_f<<<dim3(RTOT/128, 1024/64), 256>>>(cat, 512, W[4], 512, pd, 1024, 512);
    k_zero<<<1, 1024>>>(sum, sumsq);
    k_reduce5<<<dim3(BB, 4), 256>>>(pd, bmax, sum, sumsq);
    k_final<<<RTOT/256, 256>>>(bmax, sum, sumsq, ga[4], be[4], (float*)d_out);
}